// round 2
// baseline (speedup 1.0000x reference)
#include <cuda_runtime.h>
#include <math.h>

#define NTOK 8192
#define CDIM 128
#define FM   32      // queries per flash block
#define FKB  32      // keys per tile
#define SSTR 132     // padded shared row stride (floats)
#define NT   128     // flash threads per block

// Scratch (allocation-free: __device__ globals)
__device__ __align__(16) float g_X [NTOK*CDIM];
__device__ __align__(16) float g_Q [NTOK*CDIM];
__device__ __align__(16) float g_K [NTOK*CDIM];
__device__ __align__(16) float g_V [NTOK*CDIM];
__device__ __align__(16) float g_W [NTOK*CDIM];
__device__ __align__(16) float g_Y1[NTOK*256];

__device__ __forceinline__ float gelu_f(float x){
    return 0.5f * x * (1.0f + erff(x * 0.70710678118654752f));
}

__device__ __forceinline__ float dot4(float4 a, float4 b, float acc){
    acc = fmaf(a.x, b.x, acc);
    acc = fmaf(a.y, b.y, acc);
    acc = fmaf(a.z, b.z, acc);
    acc = fmaf(a.w, b.w, acc);
    return acc;
}

// out[n, c] = act( sum_k A[n,k]*B[k,c] + bias[c] )   one row per block, one col per thread
__global__ void gemm_row(const float* __restrict__ A, const float* __restrict__ B,
                         const float* __restrict__ bias, float* __restrict__ out,
                         int Kdim, int Cc, int act)
{
    __shared__ float As[128];
    int n = blockIdx.x;
    int c = threadIdx.x;
    for (int k = c; k < Kdim; k += blockDim.x) As[k] = A[n*Kdim + k];
    __syncthreads();
    float a0=0.f, a1=0.f, a2=0.f, a3=0.f;
    int k = 0;
    for (; k + 4 <= Kdim; k += 4){
        a0 = fmaf(As[k+0], B[(k+0)*Cc + c], a0);
        a1 = fmaf(As[k+1], B[(k+1)*Cc + c], a1);
        a2 = fmaf(As[k+2], B[(k+2)*Cc + c], a2);
        a3 = fmaf(As[k+3], B[(k+3)*Cc + c], a3);
    }
    for (; k < Kdim; k++) a0 = fmaf(As[k], B[k*Cc + c], a0);
    float r = (a0 + a1) + (a2 + a3) + bias[c];
    if (act) r = gelu_f(r);
    out[n*Cc + c] = r;
}

// Fused Q/K/V/W projections: one row per block, activation row loaded once.
__global__ void qkvw_kernel(const float* __restrict__ A,
                            const float* __restrict__ qw, const float* __restrict__ qb,
                            const float* __restrict__ kw, const float* __restrict__ kb,
                            const float* __restrict__ vw, const float* __restrict__ vb,
                            const float* __restrict__ ww, const float* __restrict__ wb,
                            float* __restrict__ Qo, float* __restrict__ Ko,
                            float* __restrict__ Vo, float* __restrict__ Wo)
{
    __shared__ float As[CDIM];
    const int n = blockIdx.x;
    const int c = threadIdx.x;
    As[c] = A[n*CDIM + c];
    __syncthreads();

    const float* Bm[4]   = {qw, kw, vw, ww};
    const float* bb[4]   = {qb, kb, vb, wb};
    float*       oo[4]   = {Qo, Ko, Vo, Wo};
    #pragma unroll
    for (int m = 0; m < 4; m++){
        const float* B = Bm[m];
        float a0=0.f, a1=0.f, a2=0.f, a3=0.f;
        #pragma unroll 8
        for (int k = 0; k < CDIM; k += 4){
            a0 = fmaf(As[k+0], B[(k+0)*CDIM + c], a0);
            a1 = fmaf(As[k+1], B[(k+1)*CDIM + c], a1);
            a2 = fmaf(As[k+2], B[(k+2)*CDIM + c], a2);
            a3 = fmaf(As[k+3], B[(k+3)*CDIM + c], a3);
        }
        oo[m][n*CDIM + c] = (a0 + a1) + (a2 + a3) + bb[m][c];
    }
}

// Flash attention over all 8192 keys: softmax(QK^T/sqrt(128))/N @ V, + Wres, optional GELU.
__global__ void __launch_bounds__(NT) flash_kernel(
    const float* __restrict__ Q, const float* __restrict__ K,
    const float* __restrict__ V, const float* __restrict__ Wres,
    float* __restrict__ Xout, int applyGelu)
{
    extern __shared__ float sh[];
    float* Qs     = sh;                    // FM * SSTR
    float* Ks     = sh + FM*SSTR;          // FKB * SSTR
    float* Vs     = sh + 2*FM*SSTR;        // FKB * SSTR
    float* Ss     = sh + 3*FM*SSTR;        // FM * 33
    float* sMax   = Ss + FM*33;            // FM
    float* sSum   = sMax + FM;             // FM
    float* sAlpha = sSum + FM;             // FM

    const int tid   = threadIdx.x;
    const int qbase = blockIdx.x * FM;

    // load Q tile
    for (int i = tid; i < FM*CDIM/4; i += NT){
        int r = i >> 5, c4 = i & 31;
        *(float4*)(Qs + r*SSTR + c4*4) = *(const float4*)(Q + (qbase+r)*CDIM + c4*4);
    }
    if (tid < FM){ sMax[tid] = -1e30f; sSum[tid] = 0.f; }

    const int qg   = tid >> 4;          // 0..7  -> queries 4*qg .. 4*qg+3
    const int kg   = tid & 15;          // keys 2*kg, 2*kg+1
    const int mrow = (tid >> 3) << 1;   // PV rows mrow, mrow+1
    const int dgrp = (tid & 7) << 4;    // dims dgrp .. dgrp+15

    float O0[16], O1[16];
    #pragma unroll
    for (int i = 0; i < 16; i++){ O0[i] = 0.f; O1[i] = 0.f; }

    for (int kt = 0; kt < NTOK/FKB; kt++){
        __syncthreads();
        const int kbase = kt * FKB;
        #pragma unroll
        for (int i = tid; i < FKB*CDIM/4; i += NT){
            int r = i >> 5, c4 = i & 31;
            *(float4*)(Ks + r*SSTR + c4*4) = *(const float4*)(K + (kbase+r)*CDIM + c4*4);
            *(float4*)(Vs + r*SSTR + c4*4) = *(const float4*)(V + (kbase+r)*CDIM + c4*4);
        }
        __syncthreads();

        // ---- S = Q K^T : 4x2 microtile ----
        float acc00=0.f, acc01=0.f, acc10=0.f, acc11=0.f;
        float acc20=0.f, acc21=0.f, acc30=0.f, acc31=0.f;
        const float* q0 = Qs + (4*qg+0)*SSTR;
        const float* q1 = Qs + (4*qg+1)*SSTR;
        const float* q2 = Qs + (4*qg+2)*SSTR;
        const float* q3 = Qs + (4*qg+3)*SSTR;
        const float* k0 = Ks + (2*kg)*SSTR;
        const float* k1 = k0 + SSTR;
        #pragma unroll 4
        for (int d = 0; d < CDIM; d += 4){
            float4 b0 = *(const float4*)(k0 + d);
            float4 b1 = *(const float4*)(k1 + d);
            float4 a;
            a = *(const float4*)(q0 + d); acc00 = dot4(a,b0,acc00); acc01 = dot4(a,b1,acc01);
            a = *(const float4*)(q1 + d); acc10 = dot4(a,b0,acc10); acc11 = dot4(a,b1,acc11);
            a = *(const float4*)(q2 + d); acc20 = dot4(a,b0,acc20); acc21 = dot4(a,b1,acc21);
            a = *(const float4*)(q3 + d); acc30 = dot4(a,b0,acc30); acc31 = dot4(a,b1,acc31);
        }
        const float SC = 0.08838834764831845f;  // 1/sqrt(128)
        Ss[(4*qg+0)*33 + 2*kg+0] = acc00*SC;  Ss[(4*qg+0)*33 + 2*kg+1] = acc01*SC;
        Ss[(4*qg+1)*33 + 2*kg+0] = acc10*SC;  Ss[(4*qg+1)*33 + 2*kg+1] = acc11*SC;
        Ss[(4*qg+2)*33 + 2*kg+0] = acc20*SC;  Ss[(4*qg+2)*33 + 2*kg+1] = acc21*SC;
        Ss[(4*qg+3)*33 + 2*kg+0] = acc30*SC;  Ss[(4*qg+3)*33 + 2*kg+1] = acc31*SC;
        __syncthreads();

        // ---- online softmax: 4 threads per row ----
        {
            const int row = tid >> 2, l4 = tid & 3;
            float* srow = Ss + row*33 + l4*8;
            float v0=srow[0], v1=srow[1], v2=srow[2], v3=srow[3];
            float v4=srow[4], v5=srow[5], v6=srow[6], v7=srow[7];
            float lm = fmaxf(fmaxf(fmaxf(v0,v1), fmaxf(v2,v3)),
                             fmaxf(fmaxf(v4,v5), fmaxf(v6,v7)));
            lm = fmaxf(lm, __shfl_xor_sync(0xffffffffu, lm, 2));
            lm = fmaxf(lm, __shfl_xor_sync(0xffffffffu, lm, 1));
            float om = sMax[row];
            float nm = fmaxf(om, lm);
            float p0=__expf(v0-nm), p1=__expf(v1-nm), p2=__expf(v2-nm), p3=__expf(v3-nm);
            float p4=__expf(v4-nm), p5=__expf(v5-nm), p6=__expf(v6-nm), p7=__expf(v7-nm);
            srow[0]=p0; srow[1]=p1; srow[2]=p2; srow[3]=p3;
            srow[4]=p4; srow[5]=p5; srow[6]=p6; srow[7]=p7;
            float ts = ((p0+p1)+(p2+p3)) + ((p4+p5)+(p6+p7));
            ts += __shfl_xor_sync(0xffffffffu, ts, 2);
            ts += __shfl_xor_sync(0xffffffffu, ts, 1);
            if (l4 == 0){
                float al = __expf(om - nm);
                sAlpha[row] = al;
                sSum[row]   = sSum[row]*al + ts;
                sMax[row]   = nm;
            }
        }
        __syncthreads();

        // ---- rescale + P @ V ----
        float al0 = sAlpha[mrow], al1 = sAlpha[mrow+1];
        #pragma unroll
        for (int i = 0; i < 16; i++){ O0[i] *= al0; O1[i] *= al1; }
        const float* p0r = Ss + mrow*33;
        const float* p1r = Ss + (mrow+1)*33;
        #pragma unroll 4
        for (int k2 = 0; k2 < FKB; k2++){
            float pa = p0r[k2], pb = p1r[k2];
            const float* vrow = Vs + k2*SSTR + dgrp;
            #pragma unroll
            for (int i = 0; i < 16; i += 4){
                float4 v = *(const float4*)(vrow + i);
                O0[i+0] = fmaf(pa, v.x, O0[i+0]);
                O0[i+1] = fmaf(pa, v.y, O0[i+1]);
                O0[i+2] = fmaf(pa, v.z, O0[i+2]);
                O0[i+3] = fmaf(pa, v.w, O0[i+3]);
                O1[i+0] = fmaf(pb, v.x, O1[i+0]);
                O1[i+1] = fmaf(pb, v.y, O1[i+1]);
                O1[i+2] = fmaf(pb, v.z, O1[i+2]);
                O1[i+3] = fmaf(pb, v.w, O1[i+3]);
            }
        }
    }
    __syncthreads();

    // ---- epilogue: /l /N + residual linear + optional GELU ----
    const float inv0 = 1.0f / (sSum[mrow]   * 8192.0f);
    const float inv1 = 1.0f / (sSum[mrow+1] * 8192.0f);
    const int r0 = qbase + mrow, r1 = r0 + 1;
    #pragma unroll
    for (int i = 0; i < 16; i++){
        float x0 = O0[i]*inv0 + Wres[r0*CDIM + dgrp + i];
        float x1 = O1[i]*inv1 + Wres[r1*CDIM + dgrp + i];
        if (applyGelu){ x0 = gelu_f(x0); x1 = gelu_f(x1); }
        Xout[r0*CDIM + dgrp + i] = x0;
        Xout[r1*CDIM + dgrp + i] = x1;
    }
}

// Local attention: one warp per (token, head). 32 neighbors = 32 lanes.
__global__ void local_attn_kernel(const float* __restrict__ Q, const float* __restrict__ K,
                                  const float* __restrict__ V, const float* __restrict__ Wres,
                                  const int* __restrict__ nbr, float* __restrict__ Xout)
{
    const int n    = blockIdx.x;
    const int h    = threadIdx.x >> 5;
    const int lane = threadIdx.x & 31;
    const int idx  = nbr[n*32 + lane];

    const float* qp = Q + n*CDIM   + h*16;
    const float* kp = K + idx*CDIM + h*16;
    float s = 0.f;
    #pragma unroll
    for (int d = 0; d < 16; d++) s = fmaf(qp[d], kp[d], s);
    s *= 0.25f;  // 1/sqrt(16)

    float mx = s;
    #pragma unroll
    for (int off = 16; off; off >>= 1) mx = fmaxf(mx, __shfl_xor_sync(0xffffffffu, mx, off));
    float e = __expf(s - mx);
    float tot = e;
    #pragma unroll
    for (int off = 16; off; off >>= 1) tot += __shfl_xor_sync(0xffffffffu, tot, off);
    float p = e / tot;

    const float* vp = V + idx*CDIM + h*16;
    float myout = 0.f;
    #pragma unroll
    for (int d = 0; d < 16; d++){
        float t = p * vp[d];
        #pragma unroll
        for (int off = 16; off; off >>= 1) t += __shfl_xor_sync(0xffffffffu, t, off);
        if (lane == d) myout = t;
    }
    if (lane < 16){
        int o = n*CDIM + h*16 + lane;
        Xout[o] = gelu_f(myout + Wres[o]);
    }
}

// fc2: one warp per row, dot(Y[n,:256], w) + b
__global__ void fc2_kernel(const float* __restrict__ Y, const float* __restrict__ w,
                           const float* __restrict__ b, float* __restrict__ out)
{
    const int gw   = (blockIdx.x * blockDim.x + threadIdx.x) >> 5;
    const int lane = threadIdx.x & 31;
    if (gw >= NTOK) return;
    const float* yr = Y + gw*256;
    float acc = 0.f;
    #pragma unroll
    for (int c = 0; c < 8; c++) acc = fmaf(yr[lane + 32*c], w[lane + 32*c], acc);
    #pragma unroll
    for (int off = 16; off; off >>= 1) acc += __shfl_xor_sync(0xffffffffu, acc, off);
    if (lane == 0) out[gw] = acc + b[0];
}

#define FLASH_SHBYTES ((3*FM*SSTR + FM*33 + 3*FM) * (int)sizeof(float))

extern "C" void kernel_launch(void* const* d_in, const int* in_sizes, int n_in,
                              void* d_out, int out_size)
{
    const float* x    = (const float*)d_in[0];
    const float* fc0w = (const float*)d_in[1];
    const float* fc0b = (const float*)d_in[2];
    const float* fc1w = (const float*)d_in[27];
    const float* fc1b = (const float*)d_in[28];
    const float* fc2w = (const float*)d_in[29];
    const float* fc2b = (const float*)d_in[30];
    const int*   nbr  = (const int*)d_in[31];
    float* out = (float*)d_out;

    float *X, *Qp, *Kp, *Vp, *Wp, *Y1;
    cudaGetSymbolAddress((void**)&X,  g_X);
    cudaGetSymbolAddress((void**)&Qp, g_Q);
    cudaGetSymbolAddress((void**)&Kp, g_K);
    cudaGetSymbolAddress((void**)&Vp, g_V);
    cudaGetSymbolAddress((void**)&Wp, g_W);
    cudaGetSymbolAddress((void**)&Y1, g_Y1);

    cudaFuncSetAttribute(flash_kernel, cudaFuncAttributeMaxDynamicSharedMemorySize,
                         FLASH_SHBYTES);

    // fc0: [8192,3] @ [3,128] + b
    gemm_row<<<NTOK, 128>>>(x, fc0w, fc0b, X, 3, CDIM, 0);

    for (int layer = 0; layer < 3; layer++){
        const int base = 3 + layer*8;
        const float* qw = (const float*)d_in[base+0];
        const float* qb = (const float*)d_in[base+1];
        const float* kw = (const float*)d_in[base+2];
        const float* kb = (const float*)d_in[base+3];
        const float* vw = (const float*)d_in[base+4];
        const float* vb = (const float*)d_in[base+5];
        const float* ww = (const float*)d_in[base+6];
        const float* wb = (const float*)d_in[base+7];

        qkvw_kernel<<<NTOK, 128>>>(X, qw, qb, kw, kb, vw, vb, ww, wb,
                                   Qp, Kp, Vp, Wp);

        if (layer == 1){
            local_attn_kernel<<<NTOK, 256>>>(Qp, Kp, Vp, Wp, nbr, X);
        } else {
            flash_kernel<<<NTOK/FM, NT, FLASH_SHBYTES>>>(Qp, Kp, Vp, Wp, X,
                                                         (layer == 0) ? 1 : 0);
        }
    }

    // fc1 (+GELU), fc2
    gemm_row<<<NTOK, 256>>>(X, fc1w, fc1b, Y1, CDIM, 256, 1);
    fc2_kernel<<<NTOK*32/256, 256>>>(Y1, fc2w, fc2b, out);
}

// round 12
// speedup vs baseline: 8.7785x; 8.7785x over previous
#include <cuda_runtime.h>
#include <cuda_bf16.h>
#include <math.h>
#include <stdint.h>

typedef __nv_bfloat16 bf16;

#define NTOK 8192
#define CDIM 128

// ---------------- scratch (allocation-free) ----------------
__device__ __align__(16) float g_X [NTOK*CDIM];
__device__ __align__(16) bf16  g_Qh[NTOK*CDIM];
__device__ __align__(16) bf16  g_Kh[NTOK*CDIM];
__device__ __align__(16) bf16  g_Vh[NTOK*CDIM];
__device__ __align__(16) float g_W [NTOK*CDIM];
__device__ __align__(16) float g_Y1[NTOK*256];

__device__ __forceinline__ float gelu_f(float x){
    return 0.5f * x * (1.0f + erff(x * 0.70710678118654752f));
}
__device__ __forceinline__ float ex2f(float x){
    float r; asm("ex2.approx.f32 %0, %1;" : "=f"(r) : "f"(x)); return r;
}
__device__ __forceinline__ unsigned packbf(float a, float b){
    __nv_bfloat162 h = __floats2bfloat162_rn(a, b);   // low = a, high = b
    return *(unsigned*)&h;
}
__device__ __forceinline__ void mma_bf16(float* d, const unsigned* a, unsigned b0, unsigned b1){
    asm volatile(
      "mma.sync.aligned.m16n8k16.row.col.f32.bf16.bf16.f32 "
      "{%0,%1,%2,%3}, {%4,%5,%6,%7}, {%8,%9}, {%0,%1,%2,%3};"
      : "+f"(d[0]), "+f"(d[1]), "+f"(d[2]), "+f"(d[3])
      : "r"(a[0]), "r"(a[1]), "r"(a[2]), "r"(a[3]), "r"(b0), "r"(b1));
}
__device__ __forceinline__ void ldsm4(unsigned* r, uint32_t addr){
    asm volatile("ldmatrix.sync.aligned.m8n8.x4.shared.b16 {%0,%1,%2,%3}, [%4];"
      : "=r"(r[0]), "=r"(r[1]), "=r"(r[2]), "=r"(r[3]) : "r"(addr));
}
__device__ __forceinline__ void ldsm4t(unsigned* r, uint32_t addr){
    asm volatile("ldmatrix.sync.aligned.m8n8.x4.trans.shared.b16 {%0,%1,%2,%3}, [%4];"
      : "=r"(r[0]), "=r"(r[1]), "=r"(r[2]), "=r"(r[3]) : "r"(addr));
}
__device__ __forceinline__ void cpa16(uint32_t s, const void* g){
    asm volatile("cp.async.cg.shared.global [%0], [%1], 16;" :: "r"(s), "l"(g));
}
__device__ __forceinline__ void cpa_commit(){ asm volatile("cp.async.commit_group;"); }
__device__ __forceinline__ void cpa_wait1(){ asm volatile("cp.async.wait_group 1;"); }
__device__ __forceinline__ void cpa_wait0(){ asm volatile("cp.async.wait_group 0;"); }

// ---------------- fc0: tiny K, one row per block ----------------
__global__ void gemm_row(const float* __restrict__ A, const float* __restrict__ B,
                         const float* __restrict__ bias, float* __restrict__ out,
                         int Kdim, int Cc)
{
    __shared__ float As[16];
    int n = blockIdx.x;
    int c = threadIdx.x;
    if (c < Kdim) As[c] = A[n*Kdim + c];
    __syncthreads();
    float a0 = 0.f;
    for (int k = 0; k < Kdim; k++) a0 = fmaf(As[k], B[k*Cc + c], a0);
    out[n*Cc + c] = a0 + bias[c];
}

// ---------------- fused QKVW projections, token-tiled ----------------
__global__ __launch_bounds__(128) void qkvw_tiled(
    const float* __restrict__ X,
    const float* __restrict__ qw, const float* __restrict__ qb,
    const float* __restrict__ kw, const float* __restrict__ kb,
    const float* __restrict__ vw, const float* __restrict__ vb,
    const float* __restrict__ ww, const float* __restrict__ wb,
    bf16* __restrict__ Qo, bf16* __restrict__ Ko,
    bf16* __restrict__ Vo, float* __restrict__ Wo)
{
    __shared__ float AsT[128*36];   // [k][t], padded row
    const int tid  = threadIdx.x;
    const int tok0 = blockIdx.x * 32;

    #pragma unroll
    for (int t = 0; t < 32; t++)
        AsT[tid*36 + t] = X[(tok0 + t)*CDIM + tid];
    __syncthreads();

    const float* Bm[4] = {qw, kw, vw, ww};
    const float* bb[4] = {qb, kb, vb, wb};

    #pragma unroll
    for (int m = 0; m < 4; m++){
        const float* B = Bm[m];
        float acc[32];
        #pragma unroll
        for (int t = 0; t < 32; t++) acc[t] = 0.f;
        #pragma unroll 4
        for (int k = 0; k < 128; k++){
            float w = B[k*128 + tid];
            const float4* ar = (const float4*)&AsT[k*36];
            #pragma unroll
            for (int j = 0; j < 8; j++){
                float4 a = ar[j];
                acc[4*j+0] = fmaf(a.x, w, acc[4*j+0]);
                acc[4*j+1] = fmaf(a.y, w, acc[4*j+1]);
                acc[4*j+2] = fmaf(a.z, w, acc[4*j+2]);
                acc[4*j+3] = fmaf(a.w, w, acc[4*j+3]);
            }
        }
        float bias = bb[m][tid];
        if (m == 0){
            #pragma unroll
            for (int t = 0; t < 32; t++) Qo[(tok0+t)*128 + tid] = __float2bfloat16(acc[t] + bias);
        } else if (m == 1){
            #pragma unroll
            for (int t = 0; t < 32; t++) Ko[(tok0+t)*128 + tid] = __float2bfloat16(acc[t] + bias);
        } else if (m == 2){
            #pragma unroll
            for (int t = 0; t < 32; t++) Vo[(tok0+t)*128 + tid] = __float2bfloat16(acc[t] + bias);
        } else {
            #pragma unroll
            for (int t = 0; t < 32; t++) Wo[(tok0+t)*128 + tid] = acc[t] + bias;
        }
    }
}

// ---------------- fc1: token-tiled, 256 cols ----------------
__global__ __launch_bounds__(256) void gemm_tiled_fc1(
    const float* __restrict__ X, const float* __restrict__ B,
    const float* __restrict__ bias, float* __restrict__ out)
{
    __shared__ float AsT[128*36];
    const int tid  = threadIdx.x;
    const int tok0 = blockIdx.x * 32;

    #pragma unroll
    for (int i = 0; i < 16; i++){
        int idx = tid + i*256;
        int t = idx >> 7, k = idx & 127;
        AsT[k*36 + t] = X[(tok0 + t)*CDIM + k];
    }
    __syncthreads();

    float acc[32];
    #pragma unroll
    for (int t = 0; t < 32; t++) acc[t] = 0.f;
    #pragma unroll 4
    for (int k = 0; k < 128; k++){
        float w = B[k*256 + tid];
        const float4* ar = (const float4*)&AsT[k*36];
        #pragma unroll
        for (int j = 0; j < 8; j++){
            float4 a = ar[j];
            acc[4*j+0] = fmaf(a.x, w, acc[4*j+0]);
            acc[4*j+1] = fmaf(a.y, w, acc[4*j+1]);
            acc[4*j+2] = fmaf(a.z, w, acc[4*j+2]);
            acc[4*j+3] = fmaf(a.w, w, acc[4*j+3]);
        }
    }
    float bv = bias[tid];
    #pragma unroll
    for (int t = 0; t < 32; t++)
        out[(tok0+t)*256 + tid] = gelu_f(acc[t] + bv);
}

// ---------------- tensor-core flash attention ----------------
// 64 queries/block, 64-key tiles, 4 warps (16 query rows each), bf16 mma, fp32 accum.
// smem layout (bytes): Q/P at 0 (17408), K0 @17408, V0 @34816, K1 @52224, V1 @69632.
#define FSH_TOTAL 87040
#define KSTRB 272     // 136 bf16 per row
#define PSTRB 144     // 72  bf16 per row

__global__ __launch_bounds__(128, 1) void flash_tc(
    const bf16* __restrict__ Q, const bf16* __restrict__ K,
    const bf16* __restrict__ V, const float* __restrict__ Wres,
    float* __restrict__ Xout, int applyGelu)
{
    extern __shared__ char sm[];
    const uint32_t sb = (uint32_t)__cvta_generic_to_shared(sm);

    const int tid  = threadIdx.x;
    const int w    = tid >> 5;
    const int lane = tid & 31;
    const int g    = lane >> 2;      // 0..7 (row in 8)
    const int t    = lane & 3;       // 0..3 (col group)
    const int lr   = lane & 7;
    const int grp  = lane >> 3;      // 0..3 (ldmatrix group)
    const int qbase = blockIdx.x * 64;

    // -- issue Q tile load (full 64x128 = 1024 16B chunks) --
    #pragma unroll
    for (int c = 0; c < 8; c++){
        int idx = tid + c*128;
        int row = idx >> 4, off = idx & 15;
        cpa16(sb + row*KSTRB + off*16, Q + (qbase+row)*CDIM + off*8);
    }
    cpa_commit();
    // -- issue KV tile 0 --
    #pragma unroll
    for (int c = 0; c < 8; c++){
        int idx = tid + c*128;
        int row = idx >> 4, off = idx & 15;
        cpa16(sb + 17408 + row*KSTRB + off*16, K + row*CDIM + off*8);
    }
    #pragma unroll
    for (int c = 0; c < 8; c++){
        int idx = tid + c*128;
        int row = idx >> 4, off = idx & 15;
        cpa16(sb + 34816 + row*KSTRB + off*16, V + row*CDIM + off*8);
    }
    cpa_commit();

    cpa_wait1();            // Q done (groups retire in order)
    __syncthreads();

    // -- Q fragments, register resident (8 k-tiles) --
    unsigned qf[8][4];
    {
        const uint32_t rb = sb + (16*w + lr + (grp&1)*8)*KSTRB;
        #pragma unroll
        for (int kt = 0; kt < 8; kt++)
            ldsm4(qf[kt], rb + (kt*16 + (grp>>1)*8)*2);
    }
    __syncthreads();        // Q region becomes P region after this

    float O[16][4];
    #pragma unroll
    for (int i = 0; i < 16; i++){ O[i][0]=0.f; O[i][1]=0.f; O[i][2]=0.f; O[i][3]=0.f; }
    float m_lo = -1e30f, m_hi = -1e30f, l_lo = 0.f, l_hi = 0.f;
    const float SC2 = 0.12751744458568204f;   // 1/(sqrt(128)*ln2)

    for (int it = 0; it < 128; it++){
        if (it + 1 < 128){
            const int nb = (it + 1) & 1;
            const int kb2 = (it + 1) * 64;
            #pragma unroll
            for (int c = 0; c < 8; c++){
                int idx = tid + c*128;
                int row = idx >> 4, off = idx & 15;
                cpa16(sb + 17408 + nb*34816 + row*KSTRB + off*16, K + (kb2+row)*CDIM + off*8);
            }
            #pragma unroll
            for (int c = 0; c < 8; c++){
                int idx = tid + c*128;
                int row = idx >> 4, off = idx & 15;
                cpa16(sb + 34816 + nb*34816 + row*KSTRB + off*16, V + (kb2+row)*CDIM + off*8);
            }
            cpa_commit();
            cpa_wait1();
        } else {
            cpa_wait0();
        }
        __syncthreads();

        const uint32_t kbuf = sb + 17408 + (it & 1)*34816;
        const uint32_t vbuf = kbuf + 17408;

        // ---- S = Q K^T ----
        float s[8][4];
        #pragma unroll
        for (int i = 0; i < 8; i++){ s[i][0]=0.f; s[i][1]=0.f; s[i][2]=0.f; s[i][3]=0.f; }
        #pragma unroll
        for (int np = 0; np < 4; np++){
            const uint32_t nb_addr = kbuf + (np*16 + lr + ((grp>=2)?8:0))*KSTRB;
            #pragma unroll
            for (int kt = 0; kt < 8; kt++){
                unsigned b[4];
                ldsm4(b, nb_addr + (kt*16 + (grp&1)*8)*2);
                mma_bf16(s[2*np+0], qf[kt], b[0], b[1]);
                mma_bf16(s[2*np+1], qf[kt], b[2], b[3]);
            }
        }

        // ---- online softmax (log2 domain) ----
        #pragma unroll
        for (int i = 0; i < 8; i++){
            s[i][0] *= SC2; s[i][1] *= SC2; s[i][2] *= SC2; s[i][3] *= SC2;
        }
        float mx_lo = -1e30f, mx_hi = -1e30f;
        #pragma unroll
        for (int i = 0; i < 8; i++){
            mx_lo = fmaxf(mx_lo, fmaxf(s[i][0], s[i][1]));
            mx_hi = fmaxf(mx_hi, fmaxf(s[i][2], s[i][3]));
        }
        mx_lo = fmaxf(mx_lo, __shfl_xor_sync(0xffffffffu, mx_lo, 1));
        mx_lo = fmaxf(mx_lo, __shfl_xor_sync(0xffffffffu, mx_lo, 2));
        mx_hi = fmaxf(mx_hi, __shfl_xor_sync(0xffffffffu, mx_hi, 1));
        mx_hi = fmaxf(mx_hi, __shfl_xor_sync(0xffffffffu, mx_hi, 2));
        const float nm_lo = fmaxf(m_lo, mx_lo);
        const float nm_hi = fmaxf(m_hi, mx_hi);
        const float al_lo = ex2f(m_lo - nm_lo);
        const float al_hi = ex2f(m_hi - nm_hi);
        m_lo = nm_lo; m_hi = nm_hi;

        float sum_lo = 0.f, sum_hi = 0.f;
        #pragma unroll
        for (int i = 0; i < 8; i++){
            s[i][0] = ex2f(s[i][0] - nm_lo);
            s[i][1] = ex2f(s[i][1] - nm_lo);
            s[i][2] = ex2f(s[i][2] - nm_hi);
            s[i][3] = ex2f(s[i][3] - nm_hi);
            sum_lo += s[i][0] + s[i][1];
            sum_hi += s[i][2] + s[i][3];
        }
        sum_lo += __shfl_xor_sync(0xffffffffu, sum_lo, 1);
        sum_lo += __shfl_xor_sync(0xffffffffu, sum_lo, 2);
        sum_hi += __shfl_xor_sync(0xffffffffu, sum_hi, 1);
        sum_hi += __shfl_xor_sync(0xffffffffu, sum_hi, 2);
        l_lo = l_lo * al_lo + sum_lo;
        l_hi = l_hi * al_hi + sum_hi;

        #pragma unroll
        for (int i = 0; i < 16; i++){
            O[i][0] *= al_lo; O[i][1] *= al_lo;
            O[i][2] *= al_hi; O[i][3] *= al_hi;
        }

        // ---- write P (bf16), warp-private rows ----
        {
            unsigned* Prow  = (unsigned*)(sm + (16*w + g)*PSTRB);
            unsigned* Prow8 = (unsigned*)(sm + (16*w + g + 8)*PSTRB);
            #pragma unroll
            for (int nt = 0; nt < 8; nt++){
                Prow [nt*4 + t] = packbf(s[nt][0], s[nt][1]);
                Prow8[nt*4 + t] = packbf(s[nt][2], s[nt][3]);
            }
        }
        __syncwarp();

        // ---- O += P V ----
        unsigned pa[4][4];
        {
            const uint32_t rb = sb + (16*w + lr + (grp&1)*8)*PSTRB;
            #pragma unroll
            for (int kk = 0; kk < 4; kk++)
                ldsm4(pa[kk], rb + (kk*16 + ((grp>=2)?8:0))*2);
        }
        #pragma unroll
        for (int np = 0; np < 8; np++){
            #pragma unroll
            for (int kk = 0; kk < 4; kk++){
                unsigned b[4];
                ldsm4t(b, vbuf + (kk*16 + lr + (grp&1)*8)*KSTRB + (np*16 + ((grp>=2)?8:0))*2);
                mma_bf16(O[2*np+0], pa[kk], b[0], b[1]);
                mma_bf16(O[2*np+1], pa[kk], b[2], b[3]);
            }
        }
        __syncthreads();
    }

    // ---- epilogue: /(l*N) + residual + optional GELU ----
    const float inv_lo = 1.0f / (l_lo * 8192.0f);
    const float inv_hi = 1.0f / (l_hi * 8192.0f);
    const int r_lo = qbase + 16*w + g;
    const int r_hi = r_lo + 8;
    #pragma unroll
    for (int nt = 0; nt < 16; nt++){
        const int d0 = nt*8 + 2*t;
        float x0 = O[nt][0]*inv_lo + Wres[r_lo*CDIM + d0];
        float x1 = O[nt][1]*inv_lo + Wres[r_lo*CDIM + d0 + 1];
        float x2 = O[nt][2]*inv_hi + Wres[r_hi*CDIM + d0];
        float x3 = O[nt][3]*inv_hi + Wres[r_hi*CDIM + d0 + 1];
        if (applyGelu){ x0 = gelu_f(x0); x1 = gelu_f(x1); x2 = gelu_f(x2); x3 = gelu_f(x3); }
        Xout[r_lo*CDIM + d0]     = x0;
        Xout[r_lo*CDIM + d0 + 1] = x1;
        Xout[r_hi*CDIM + d0]     = x2;
        Xout[r_hi*CDIM + d0 + 1] = x3;
    }
}

// ---------------- local attention (bf16 inputs) ----------------
__global__ void local_attn_kernel(const bf16* __restrict__ Q, const bf16* __restrict__ K,
                                  const bf16* __restrict__ V, const float* __restrict__ Wres,
                                  const int* __restrict__ nbr, float* __restrict__ Xout)
{
    const int n    = blockIdx.x;
    const int h    = threadIdx.x >> 5;
    const int lane = threadIdx.x & 31;
    const int idx  = nbr[n*32 + lane];

    const bf16* qp = Q + n*CDIM   + h*16;
    const bf16* kp = K + idx*CDIM + h*16;
    float s = 0.f;
    #pragma unroll
    for (int d = 0; d < 16; d++)
        s = fmaf(__bfloat162float(qp[d]), __bfloat162float(kp[d]), s);
    s *= 0.25f;  // 1/sqrt(16)

    float mx = s;
    #pragma unroll
    for (int off = 16; off; off >>= 1) mx = fmaxf(mx, __shfl_xor_sync(0xffffffffu, mx, off));
    float e = __expf(s - mx);
    float tot = e;
    #pragma unroll
    for (int off = 16; off; off >>= 1) tot += __shfl_xor_sync(0xffffffffu, tot, off);
    float p = e / tot;

    const bf16* vp = V + idx*CDIM + h*16;
    float myout = 0.f;
    #pragma unroll
    for (int d = 0; d < 16; d++){
        float tsum = p * __bfloat162float(vp[d]);
        #pragma unroll
        for (int off = 16; off; off >>= 1) tsum += __shfl_xor_sync(0xffffffffu, tsum, off);
        if (lane == d) myout = tsum;
    }
    if (lane < 16){
        int o = n*CDIM + h*16 + lane;
        Xout[o] = gelu_f(myout + Wres[o]);
    }
}

// ---------------- fc2 ----------------
__global__ void fc2_kernel(const float* __restrict__ Y, const float* __restrict__ w,
                           const float* __restrict__ b, float* __restrict__ out)
{
    const int gw   = (blockIdx.x * blockDim.x + threadIdx.x) >> 5;
    const int lane = threadIdx.x & 31;
    if (gw >= NTOK) return;
    const float* yr = Y + gw*256;
    float acc = 0.f;
    #pragma unroll
    for (int c = 0; c < 8; c++) acc = fmaf(yr[lane + 32*c], w[lane + 32*c], acc);
    #pragma unroll
    for (int off = 16; off; off >>= 1) acc += __shfl_xor_sync(0xffffffffu, acc, off);
    if (lane == 0) out[gw] = acc + b[0];
}

extern "C" void kernel_launch(void* const* d_in, const int* in_sizes, int n_in,
                              void* d_out, int out_size)
{
    const float* x    = (const float*)d_in[0];
    const float* fc0w = (const float*)d_in[1];
    const float* fc0b = (const float*)d_in[2];
    const float* fc1w = (const float*)d_in[27];
    const float* fc1b = (const float*)d_in[28];
    const float* fc2w = (const float*)d_in[29];
    const float* fc2b = (const float*)d_in[30];
    const int*   nbr  = (const int*)d_in[31];
    float* out = (float*)d_out;

    float *X, *Wp, *Y1;
    bf16 *Qh, *Kh, *Vh;
    cudaGetSymbolAddress((void**)&X,  g_X);
    cudaGetSymbolAddress((void**)&Qh, g_Qh);
    cudaGetSymbolAddress((void**)&Kh, g_Kh);
    cudaGetSymbolAddress((void**)&Vh, g_Vh);
    cudaGetSymbolAddress((void**)&Wp, g_W);
    cudaGetSymbolAddress((void**)&Y1, g_Y1);

    cudaFuncSetAttribute(flash_tc, cudaFuncAttributeMaxDynamicSharedMemorySize, FSH_TOTAL);

    // fc0: [8192,3] @ [3,128] + b
    gemm_row<<<NTOK, 128>>>(x, fc0w, fc0b, X, 3, CDIM);

    for (int layer = 0; layer < 3; layer++){
        const int base = 3 + layer*8;
        qkvw_tiled<<<NTOK/32, 128>>>(X,
            (const float*)d_in[base+0], (const float*)d_in[base+1],
            (const float*)d_in[base+2], (const float*)d_in[base+3],
            (const float*)d_in[base+4], (const float*)d_in[base+5],
            (const float*)d_in[base+6], (const float*)d_in[base+7],
            Qh, Kh, Vh, Wp);

        if (layer == 1){
            local_attn_kernel<<<NTOK, 256>>>(Qh, Kh, Vh, Wp, nbr, X);
        } else {
            flash_tc<<<NTOK/64, 128, FSH_TOTAL>>>(Qh, Kh, Vh, Wp, X, (layer == 0) ? 1 : 0);
        }
    }

    gemm_tiled_fc1<<<NTOK/32, 256>>>(X, fc1w, fc1b, Y1);
    fc2_kernel<<<NTOK*32/256, 256>>>(Y1, fc2w, fc2b, out);
}

// round 13
// speedup vs baseline: 9.4251x; 1.0737x over previous
#include <cuda_runtime.h>
#include <cuda_bf16.h>
#include <math.h>
#include <stdint.h>

typedef __nv_bfloat16 bf16;

#define NTOK 8192
#define CDIM 128

// ---------------- scratch (allocation-free) ----------------
__device__ __align__(16) float g_X [NTOK*CDIM];
__device__ __align__(16) bf16  g_Qh[NTOK*CDIM];
__device__ __align__(16) bf16  g_Kh[NTOK*CDIM];
__device__ __align__(16) bf16  g_Vh[NTOK*CDIM];
__device__ __align__(16) float g_W [NTOK*CDIM];
__device__ __align__(16) float g_Y1[NTOK*256];

__device__ __forceinline__ float gelu_f(float x){
    return 0.5f * x * (1.0f + erff(x * 0.70710678118654752f));
}
__device__ __forceinline__ float ex2f(float x){
    float r; asm("ex2.approx.f32 %0, %1;" : "=f"(r) : "f"(x)); return r;
}
__device__ __forceinline__ unsigned packbf(float a, float b){
    __nv_bfloat162 h = __floats2bfloat162_rn(a, b);   // low = a, high = b
    return *(unsigned*)&h;
}
__device__ __forceinline__ void mma_bf16(float* d, const unsigned* a, unsigned b0, unsigned b1){
    asm volatile(
      "mma.sync.aligned.m16n8k16.row.col.f32.bf16.bf16.f32 "
      "{%0,%1,%2,%3}, {%4,%5,%6,%7}, {%8,%9}, {%0,%1,%2,%3};"
      : "+f"(d[0]), "+f"(d[1]), "+f"(d[2]), "+f"(d[3])
      : "r"(a[0]), "r"(a[1]), "r"(a[2]), "r"(a[3]), "r"(b0), "r"(b1));
}
__device__ __forceinline__ void ldsm4(unsigned* r, uint32_t addr){
    asm volatile("ldmatrix.sync.aligned.m8n8.x4.shared.b16 {%0,%1,%2,%3}, [%4];"
      : "=r"(r[0]), "=r"(r[1]), "=r"(r[2]), "=r"(r[3]) : "r"(addr));
}
__device__ __forceinline__ void ldsm4t(unsigned* r, uint32_t addr){
    asm volatile("ldmatrix.sync.aligned.m8n8.x4.trans.shared.b16 {%0,%1,%2,%3}, [%4];"
      : "=r"(r[0]), "=r"(r[1]), "=r"(r[2]), "=r"(r[3]) : "r"(addr));
}
__device__ __forceinline__ void cpa16(uint32_t s, const void* g){
    asm volatile("cp.async.cg.shared.global [%0], [%1], 16;" :: "r"(s), "l"(g));
}
__device__ __forceinline__ void cpa_commit(){ asm volatile("cp.async.commit_group;"); }
__device__ __forceinline__ void cpa_wait1(){ asm volatile("cp.async.wait_group 1;"); }
__device__ __forceinline__ void cpa_wait0(){ asm volatile("cp.async.wait_group 0;"); }

// ---------------- fc0: tiny K, one row per block ----------------
__global__ void gemm_row(const float* __restrict__ A, const float* __restrict__ B,
                         const float* __restrict__ bias, float* __restrict__ out,
                         int Kdim, int Cc)
{
    __shared__ float As[16];
    int n = blockIdx.x;
    int c = threadIdx.x;
    if (c < Kdim) As[c] = A[n*Kdim + c];
    __syncthreads();
    float a0 = 0.f;
    for (int k = 0; k < Kdim; k++) a0 = fmaf(As[k], B[k*Cc + c], a0);
    out[n*Cc + c] = a0 + bias[c];
}

// ---------------- fused QKVW projections, one matrix per blockIdx.y ----------------
// grid (NTOK/32, 4): 4x the blocks in flight vs the m-loop version -> hides LDG latency.
__global__ __launch_bounds__(128) void qkvw_tiled(
    const float* __restrict__ X,
    const float* __restrict__ qw, const float* __restrict__ qb,
    const float* __restrict__ kw, const float* __restrict__ kb,
    const float* __restrict__ vw, const float* __restrict__ vb,
    const float* __restrict__ ww, const float* __restrict__ wb,
    bf16* __restrict__ Qo, bf16* __restrict__ Ko,
    bf16* __restrict__ Vo, float* __restrict__ Wo)
{
    __shared__ float AsT[128*36];   // [k][t], padded row
    const int tid  = threadIdx.x;
    const int tok0 = blockIdx.x * 32;
    const int m    = blockIdx.y;

    #pragma unroll
    for (int t = 0; t < 32; t++)
        AsT[tid*36 + t] = X[(tok0 + t)*CDIM + tid];
    __syncthreads();

    const float* B  = (m == 0) ? qw : (m == 1) ? kw : (m == 2) ? vw : ww;
    const float* bi = (m == 0) ? qb : (m == 1) ? kb : (m == 2) ? vb : wb;

    float acc[32];
    #pragma unroll
    for (int t = 0; t < 32; t++) acc[t] = 0.f;
    #pragma unroll 4
    for (int k = 0; k < 128; k++){
        float w = B[k*128 + tid];
        const float4* ar = (const float4*)&AsT[k*36];
        #pragma unroll
        for (int j = 0; j < 8; j++){
            float4 a = ar[j];
            acc[4*j+0] = fmaf(a.x, w, acc[4*j+0]);
            acc[4*j+1] = fmaf(a.y, w, acc[4*j+1]);
            acc[4*j+2] = fmaf(a.z, w, acc[4*j+2]);
            acc[4*j+3] = fmaf(a.w, w, acc[4*j+3]);
        }
    }
    float bias = bi[tid];
    if (m == 3){
        #pragma unroll
        for (int t = 0; t < 32; t++) Wo[(tok0+t)*128 + tid] = acc[t] + bias;
    } else {
        bf16* O = (m == 0) ? Qo : (m == 1) ? Ko : Vo;
        #pragma unroll
        for (int t = 0; t < 32; t++) O[(tok0+t)*128 + tid] = __float2bfloat16(acc[t] + bias);
    }
}

// ---------------- fc1: 16 tokens/block, 256 cols ----------------
__global__ __launch_bounds__(256) void gemm_tiled_fc1(
    const float* __restrict__ X, const float* __restrict__ B,
    const float* __restrict__ bias, float* __restrict__ out)
{
    __shared__ float AsT[128*20];   // [k][t] 16 tokens + 4 pad
    const int tid  = threadIdx.x;
    const int tok0 = blockIdx.x * 16;

    #pragma unroll
    for (int i = 0; i < 8; i++){
        int idx = tid + i*256;
        int t = idx >> 7, k = idx & 127;
        AsT[k*20 + t] = X[(tok0 + t)*CDIM + k];
    }
    __syncthreads();

    float acc[16];
    #pragma unroll
    for (int t = 0; t < 16; t++) acc[t] = 0.f;
    #pragma unroll 4
    for (int k = 0; k < 128; k++){
        float w = B[k*256 + tid];
        const float4* ar = (const float4*)&AsT[k*20];
        #pragma unroll
        for (int j = 0; j < 4; j++){
            float4 a = ar[j];
            acc[4*j+0] = fmaf(a.x, w, acc[4*j+0]);
            acc[4*j+1] = fmaf(a.y, w, acc[4*j+1]);
            acc[4*j+2] = fmaf(a.z, w, acc[4*j+2]);
            acc[4*j+3] = fmaf(a.w, w, acc[4*j+3]);
        }
    }
    float bv = bias[tid];
    #pragma unroll
    for (int t = 0; t < 16; t++)
        out[(tok0+t)*256 + tid] = gelu_f(acc[t] + bv);
}

// ---------------- tensor-core flash attention ----------------
// 64 queries/block, 64-key tiles, 4 warps (16 query rows each), bf16 mma, fp32 accum.
// smem layout (bytes): Q/P at 0 (17408), K0 @17408, V0 @34816, K1 @52224, V1 @69632.
#define FSH_TOTAL 87040
#define KSTRB 272     // 136 bf16 per row
#define PSTRB 144     // 72  bf16 per row

__global__ __launch_bounds__(128, 1) void flash_tc(
    const bf16* __restrict__ Q, const bf16* __restrict__ K,
    const bf16* __restrict__ V, const float* __restrict__ Wres,
    float* __restrict__ Xout, int applyGelu)
{
    extern __shared__ char sm[];
    const uint32_t sb = (uint32_t)__cvta_generic_to_shared(sm);

    const int tid  = threadIdx.x;
    const int w    = tid >> 5;
    const int lane = tid & 31;
    const int g    = lane >> 2;      // 0..7 (row in 8)
    const int t    = lane & 3;       // 0..3 (col group)
    const int lr   = lane & 7;
    const int grp  = lane >> 3;      // 0..3 (ldmatrix group)
    const int qbase = blockIdx.x * 64;

    // -- issue Q tile load (full 64x128 = 1024 16B chunks) --
    #pragma unroll
    for (int c = 0; c < 8; c++){
        int idx = tid + c*128;
        int row = idx >> 4, off = idx & 15;
        cpa16(sb + row*KSTRB + off*16, Q + (qbase+row)*CDIM + off*8);
    }
    cpa_commit();
    // -- issue KV tile 0 --
    #pragma unroll
    for (int c = 0; c < 8; c++){
        int idx = tid + c*128;
        int row = idx >> 4, off = idx & 15;
        cpa16(sb + 17408 + row*KSTRB + off*16, K + row*CDIM + off*8);
    }
    #pragma unroll
    for (int c = 0; c < 8; c++){
        int idx = tid + c*128;
        int row = idx >> 4, off = idx & 15;
        cpa16(sb + 34816 + row*KSTRB + off*16, V + row*CDIM + off*8);
    }
    cpa_commit();

    cpa_wait1();            // Q done (groups retire in order)
    __syncthreads();

    // -- Q fragments, register resident (8 k-tiles) --
    unsigned qf[8][4];
    {
        const uint32_t rb = sb + (16*w + lr + (grp&1)*8)*KSTRB;
        #pragma unroll
        for (int kt = 0; kt < 8; kt++)
            ldsm4(qf[kt], rb + (kt*16 + (grp>>1)*8)*2);
    }
    __syncthreads();        // Q region becomes P region after this

    float O[16][4];
    #pragma unroll
    for (int i = 0; i < 16; i++){ O[i][0]=0.f; O[i][1]=0.f; O[i][2]=0.f; O[i][3]=0.f; }
    float m_lo = -1e30f, m_hi = -1e30f, l_lo = 0.f, l_hi = 0.f;
    const float SC2 = 0.12751744458568204f;   // 1/(sqrt(128)*ln2)

    for (int it = 0; it < 128; it++){
        if (it + 1 < 128){
            const int nb = (it + 1) & 1;
            const int kb2 = (it + 1) * 64;
            #pragma unroll
            for (int c = 0; c < 8; c++){
                int idx = tid + c*128;
                int row = idx >> 4, off = idx & 15;
                cpa16(sb + 17408 + nb*34816 + row*KSTRB + off*16, K + (kb2+row)*CDIM + off*8);
            }
            #pragma unroll
            for (int c = 0; c < 8; c++){
                int idx = tid + c*128;
                int row = idx >> 4, off = idx & 15;
                cpa16(sb + 34816 + nb*34816 + row*KSTRB + off*16, V + (kb2+row)*CDIM + off*8);
            }
            cpa_commit();
            cpa_wait1();
        } else {
            cpa_wait0();
        }
        __syncthreads();

        const uint32_t kbuf = sb + 17408 + (it & 1)*34816;
        const uint32_t vbuf = kbuf + 17408;

        // ---- S = Q K^T ----
        float s[8][4];
        #pragma unroll
        for (int i = 0; i < 8; i++){ s[i][0]=0.f; s[i][1]=0.f; s[i][2]=0.f; s[i][3]=0.f; }
        #pragma unroll
        for (int np = 0; np < 4; np++){
            const uint32_t nb_addr = kbuf + (np*16 + lr + ((grp>=2)?8:0))*KSTRB;
            #pragma unroll
            for (int kt = 0; kt < 8; kt++){
                unsigned b[4];
                ldsm4(b, nb_addr + (kt*16 + (grp&1)*8)*2);
                mma_bf16(s[2*np+0], qf[kt], b[0], b[1]);
                mma_bf16(s[2*np+1], qf[kt], b[2], b[3]);
            }
        }

        // ---- online softmax (log2 domain) ----
        #pragma unroll
        for (int i = 0; i < 8; i++){
            s[i][0] *= SC2; s[i][1] *= SC2; s[i][2] *= SC2; s[i][3] *= SC2;
        }
        float mx_lo = -1e30f, mx_hi = -1e30f;
        #pragma unroll
        for (int i = 0; i < 8; i++){
            mx_lo = fmaxf(mx_lo, fmaxf(s[i][0], s[i][1]));
            mx_hi = fmaxf(mx_hi, fmaxf(s[i][2], s[i][3]));
        }
        mx_lo = fmaxf(mx_lo, __shfl_xor_sync(0xffffffffu, mx_lo, 1));
        mx_lo = fmaxf(mx_lo, __shfl_xor_sync(0xffffffffu, mx_lo, 2));
        mx_hi = fmaxf(mx_hi, __shfl_xor_sync(0xffffffffu, mx_hi, 1));
        mx_hi = fmaxf(mx_hi, __shfl_xor_sync(0xffffffffu, mx_hi, 2));
        const float nm_lo = fmaxf(m_lo, mx_lo);
        const float nm_hi = fmaxf(m_hi, mx_hi);
        const float al_lo = ex2f(m_lo - nm_lo);
        const float al_hi = ex2f(m_hi - nm_hi);
        m_lo = nm_lo; m_hi = nm_hi;

        float sum_lo = 0.f, sum_hi = 0.f;
        #pragma unroll
        for (int i = 0; i < 8; i++){
            s[i][0] = ex2f(s[i][0] - nm_lo);
            s[i][1] = ex2f(s[i][1] - nm_lo);
            s[i][2] = ex2f(s[i][2] - nm_hi);
            s[i][3] = ex2f(s[i][3] - nm_hi);
            sum_lo += s[i][0] + s[i][1];
            sum_hi += s[i][2] + s[i][3];
        }
        sum_lo += __shfl_xor_sync(0xffffffffu, sum_lo, 1);
        sum_lo += __shfl_xor_sync(0xffffffffu, sum_lo, 2);
        sum_hi += __shfl_xor_sync(0xffffffffu, sum_hi, 1);
        sum_hi += __shfl_xor_sync(0xffffffffu, sum_hi, 2);
        l_lo = l_lo * al_lo + sum_lo;
        l_hi = l_hi * al_hi + sum_hi;

        #pragma unroll
        for (int i = 0; i < 16; i++){
            O[i][0] *= al_lo; O[i][1] *= al_lo;
            O[i][2] *= al_hi; O[i][3] *= al_hi;
        }

        // ---- write P (bf16), warp-private rows ----
        {
            unsigned* Prow  = (unsigned*)(sm + (16*w + g)*PSTRB);
            unsigned* Prow8 = (unsigned*)(sm + (16*w + g + 8)*PSTRB);
            #pragma unroll
            for (int nt = 0; nt < 8; nt++){
                Prow [nt*4 + t] = packbf(s[nt][0], s[nt][1]);
                Prow8[nt*4 + t] = packbf(s[nt][2], s[nt][3]);
            }
        }
        __syncwarp();

        // ---- O += P V ----
        unsigned pa[4][4];
        {
            const uint32_t rb = sb + (16*w + lr + (grp&1)*8)*PSTRB;
            #pragma unroll
            for (int kk = 0; kk < 4; kk++)
                ldsm4(pa[kk], rb + (kk*16 + ((grp>=2)?8:0))*2);
        }
        #pragma unroll
        for (int np = 0; np < 8; np++){
            #pragma unroll
            for (int kk = 0; kk < 4; kk++){
                unsigned b[4];
                ldsm4t(b, vbuf + (kk*16 + lr + (grp&1)*8)*KSTRB + (np*16 + ((grp>=2)?8:0))*2);
                mma_bf16(O[2*np+0], pa[kk], b[0], b[1]);
                mma_bf16(O[2*np+1], pa[kk], b[2], b[3]);
            }
        }
        __syncthreads();
    }

    // ---- epilogue: /(l*N) + residual + optional GELU ----
    const float inv_lo = 1.0f / (l_lo * 8192.0f);
    const float inv_hi = 1.0f / (l_hi * 8192.0f);
    const int r_lo = qbase + 16*w + g;
    const int r_hi = r_lo + 8;
    #pragma unroll
    for (int nt = 0; nt < 16; nt++){
        const int d0 = nt*8 + 2*t;
        float x0 = O[nt][0]*inv_lo + Wres[r_lo*CDIM + d0];
        float x1 = O[nt][1]*inv_lo + Wres[r_lo*CDIM + d0 + 1];
        float x2 = O[nt][2]*inv_hi + Wres[r_hi*CDIM + d0];
        float x3 = O[nt][3]*inv_hi + Wres[r_hi*CDIM + d0 + 1];
        if (applyGelu){ x0 = gelu_f(x0); x1 = gelu_f(x1); x2 = gelu_f(x2); x3 = gelu_f(x3); }
        Xout[r_lo*CDIM + d0]     = x0;
        Xout[r_lo*CDIM + d0 + 1] = x1;
        Xout[r_hi*CDIM + d0]     = x2;
        Xout[r_hi*CDIM + d0 + 1] = x3;
    }
}

// ---------------- local attention (bf16 inputs) ----------------
__global__ void local_attn_kernel(const bf16* __restrict__ Q, const bf16* __restrict__ K,
                                  const bf16* __restrict__ V, const float* __restrict__ Wres,
                                  const int* __restrict__ nbr, float* __restrict__ Xout)
{
    const int n    = blockIdx.x;
    const int h    = threadIdx.x >> 5;
    const int lane = threadIdx.x & 31;
    const int idx  = nbr[n*32 + lane];

    const bf16* qp = Q + n*CDIM   + h*16;
    const bf16* kp = K + idx*CDIM + h*16;
    float s = 0.f;
    #pragma unroll
    for (int d = 0; d < 16; d++)
        s = fmaf(__bfloat162float(qp[d]), __bfloat162float(kp[d]), s);
    s *= 0.25f;  // 1/sqrt(16)

    float mx = s;
    #pragma unroll
    for (int off = 16; off; off >>= 1) mx = fmaxf(mx, __shfl_xor_sync(0xffffffffu, mx, off));
    float e = __expf(s - mx);
    float tot = e;
    #pragma unroll
    for (int off = 16; off; off >>= 1) tot += __shfl_xor_sync(0xffffffffu, tot, off);
    float p = e / tot;

    const bf16* vp = V + idx*CDIM + h*16;
    float myout = 0.f;
    #pragma unroll
    for (int d = 0; d < 16; d++){
        float tsum = p * __bfloat162float(vp[d]);
        #pragma unroll
        for (int off = 16; off; off >>= 1) tsum += __shfl_xor_sync(0xffffffffu, tsum, off);
        if (lane == d) myout = tsum;
    }
    if (lane < 16){
        int o = n*CDIM + h*16 + lane;
        Xout[o] = gelu_f(myout + Wres[o]);
    }
}

// ---------------- fc2 ----------------
__global__ void fc2_kernel(const float* __restrict__ Y, const float* __restrict__ w,
                           const float* __restrict__ b, float* __restrict__ out)
{
    const int gw   = (blockIdx.x * blockDim.x + threadIdx.x) >> 5;
    const int lane = threadIdx.x & 31;
    if (gw >= NTOK) return;
    const float* yr = Y + gw*256;
    float acc = 0.f;
    #pragma unroll
    for (int c = 0; c < 8; c++) acc = fmaf(yr[lane + 32*c], w[lane + 32*c], acc);
    #pragma unroll
    for (int off = 16; off; off >>= 1) acc += __shfl_xor_sync(0xffffffffu, acc, off);
    if (lane == 0) out[gw] = acc + b[0];
}

extern "C" void kernel_launch(void* const* d_in, const int* in_sizes, int n_in,
                              void* d_out, int out_size)
{
    const float* x    = (const float*)d_in[0];
    const float* fc0w = (const float*)d_in[1];
    const float* fc0b = (const float*)d_in[2];
    const float* fc1w = (const float*)d_in[27];
    const float* fc1b = (const float*)d_in[28];
    const float* fc2w = (const float*)d_in[29];
    const float* fc2b = (const float*)d_in[30];
    const int*   nbr  = (const int*)d_in[31];
    float* out = (float*)d_out;

    float *X, *Wp, *Y1;
    bf16 *Qh, *Kh, *Vh;
    cudaGetSymbolAddress((void**)&X,  g_X);
    cudaGetSymbolAddress((void**)&Qh, g_Qh);
    cudaGetSymbolAddress((void**)&Kh, g_Kh);
    cudaGetSymbolAddress((void**)&Vh, g_Vh);
    cudaGetSymbolAddress((void**)&Wp, g_W);
    cudaGetSymbolAddress((void**)&Y1, g_Y1);

    cudaFuncSetAttribute(flash_tc, cudaFuncAttributeMaxDynamicSharedMemorySize, FSH_TOTAL);

    // fc0: [8192,3] @ [3,128] + b
    gemm_row<<<NTOK, 128>>>(x, fc0w, fc0b, X, 3, CDIM);

    for (int layer = 0; layer < 3; layer++){
        const int base = 3 + layer*8;
        qkvw_tiled<<<dim3(NTOK/32, 4), 128>>>(X,
            (const float*)d_in[base+0], (const float*)d_in[base+1],
            (const float*)d_in[base+2], (const float*)d_in[base+3],
            (const float*)d_in[base+4], (const float*)d_in[base+5],
            (const float*)d_in[base+6], (const float*)d_in[base+7],
            Qh, Kh, Vh, Wp);

        if (layer == 1){
            local_attn_kernel<<<NTOK, 256>>>(Qh, Kh, Vh, Wp, nbr, X);
        } else {
            flash_tc<<<NTOK/64, 128, FSH_TOTAL>>>(Qh, Kh, Vh, Wp, X, (layer == 0) ? 1 : 0);
        }
    }

    gemm_tiled_fc1<<<NTOK/16, 256>>>(X, fc1w, fc1b, Y1);
    fc2_kernel<<<NTOK*32/256, 256>>>(Y1, fc2w, fc2b, out);
}

// round 16
// speedup vs baseline: 10.1838x; 1.0805x over previous
#include <cuda_runtime.h>
#include <cuda_bf16.h>
#include <math.h>
#include <stdint.h>

typedef __nv_bfloat16 bf16;

#define NTOK 8192
#define CDIM 128
#define KSPLIT 4
#define KV_PER_SPLIT (NTOK/KSPLIT)   // 2048
#define ITERS_PER_SPLIT (KV_PER_SPLIT/64)  // 32

// ---------------- scratch (allocation-free) ----------------
__device__ __align__(16) float g_X [NTOK*CDIM];
__device__ __align__(16) bf16  g_Qh[NTOK*CDIM];
__device__ __align__(16) bf16  g_Kh[NTOK*CDIM];
__device__ __align__(16) bf16  g_Vh[NTOK*CDIM];
__device__ __align__(16) float g_W [NTOK*CDIM];
__device__ __align__(16) float g_Y1[NTOK*256];
__device__ __align__(16) float g_Op[KSPLIT*NTOK*CDIM];  // split partial O
__device__ __align__(16) float g_Mp[KSPLIT*NTOK];        // split row max (log2 domain)
__device__ __align__(16) float g_Lp[KSPLIT*NTOK];        // split row sum

__device__ __forceinline__ float gelu_f(float x){
    return 0.5f * x * (1.0f + erff(x * 0.70710678118654752f));
}
__device__ __forceinline__ float ex2f(float x){
    float r; asm("ex2.approx.f32 %0, %1;" : "=f"(r) : "f"(x)); return r;
}
__device__ __forceinline__ unsigned packbf(float a, float b){
    __nv_bfloat162 h = __floats2bfloat162_rn(a, b);   // low = a, high = b
    return *(unsigned*)&h;
}
__device__ __forceinline__ void mma_bf16(float* d, const unsigned* a, unsigned b0, unsigned b1){
    asm volatile(
      "mma.sync.aligned.m16n8k16.row.col.f32.bf16.bf16.f32 "
      "{%0,%1,%2,%3}, {%4,%5,%6,%7}, {%8,%9}, {%0,%1,%2,%3};"
      : "+f"(d[0]), "+f"(d[1]), "+f"(d[2]), "+f"(d[3])
      : "r"(a[0]), "r"(a[1]), "r"(a[2]), "r"(a[3]), "r"(b0), "r"(b1));
}
__device__ __forceinline__ void ldsm4(unsigned* r, uint32_t addr){
    asm volatile("ldmatrix.sync.aligned.m8n8.x4.shared.b16 {%0,%1,%2,%3}, [%4];"
      : "=r"(r[0]), "=r"(r[1]), "=r"(r[2]), "=r"(r[3]) : "r"(addr));
}
__device__ __forceinline__ void ldsm4t(unsigned* r, uint32_t addr){
    asm volatile("ldmatrix.sync.aligned.m8n8.x4.trans.shared.b16 {%0,%1,%2,%3}, [%4];"
      : "=r"(r[0]), "=r"(r[1]), "=r"(r[2]), "=r"(r[3]) : "r"(addr));
}
__device__ __forceinline__ void cpa16(uint32_t s, const void* g){
    asm volatile("cp.async.cg.shared.global [%0], [%1], 16;" :: "r"(s), "l"(g));
}
__device__ __forceinline__ void cpa_commit(){ asm volatile("cp.async.commit_group;"); }
__device__ __forceinline__ void cpa_wait1(){ asm volatile("cp.async.wait_group 1;"); }
__device__ __forceinline__ void cpa_wait0(){ asm volatile("cp.async.wait_group 0;"); }

// ---------------- fc0: tiny K, one row per block ----------------
__global__ void gemm_row(const float* __restrict__ A, const float* __restrict__ B,
                         const float* __restrict__ bias, float* __restrict__ out,
                         int Kdim, int Cc)
{
    __shared__ float As[16];
    int n = blockIdx.x;
    int c = threadIdx.x;
    if (c < Kdim) As[c] = A[n*Kdim + c];
    __syncthreads();
    float a0 = 0.f;
    for (int k = 0; k < Kdim; k++) a0 = fmaf(As[k], B[k*Cc + c], a0);
    out[n*Cc + c] = a0 + bias[c];
}

// ---------------- fused QKVW projections, one matrix per blockIdx.y ----------------
__global__ __launch_bounds__(128) void qkvw_tiled(
    const float* __restrict__ X,
    const float* __restrict__ qw, const float* __restrict__ qb,
    const float* __restrict__ kw, const float* __restrict__ kb,
    const float* __restrict__ vw, const float* __restrict__ vb,
    const float* __restrict__ ww, const float* __restrict__ wb,
    bf16* __restrict__ Qo, bf16* __restrict__ Ko,
    bf16* __restrict__ Vo, float* __restrict__ Wo)
{
    __shared__ float AsT[128*36];   // [k][t], padded row
    const int tid  = threadIdx.x;
    const int tok0 = blockIdx.x * 32;
    const int m    = blockIdx.y;

    #pragma unroll
    for (int t = 0; t < 32; t++)
        AsT[tid*36 + t] = X[(tok0 + t)*CDIM + tid];
    __syncthreads();

    const float* B  = (m == 0) ? qw : (m == 1) ? kw : (m == 2) ? vw : ww;
    const float* bi = (m == 0) ? qb : (m == 1) ? kb : (m == 2) ? vb : wb;

    float acc[32];
    #pragma unroll
    for (int t = 0; t < 32; t++) acc[t] = 0.f;
    #pragma unroll 4
    for (int k = 0; k < 128; k++){
        float w = B[k*128 + tid];
        const float4* ar = (const float4*)&AsT[k*36];
        #pragma unroll
        for (int j = 0; j < 8; j++){
            float4 a = ar[j];
            acc[4*j+0] = fmaf(a.x, w, acc[4*j+0]);
            acc[4*j+1] = fmaf(a.y, w, acc[4*j+1]);
            acc[4*j+2] = fmaf(a.z, w, acc[4*j+2]);
            acc[4*j+3] = fmaf(a.w, w, acc[4*j+3]);
        }
    }
    float bias = bi[tid];
    if (m == 3){
        #pragma unroll
        for (int t = 0; t < 32; t++) Wo[(tok0+t)*128 + tid] = acc[t] + bias;
    } else {
        bf16* O = (m == 0) ? Qo : (m == 1) ? Ko : Vo;
        #pragma unroll
        for (int t = 0; t < 32; t++) O[(tok0+t)*128 + tid] = __float2bfloat16(acc[t] + bias);
    }
}

// ---------------- fc1: 16 tokens/block, 256 cols ----------------
__global__ __launch_bounds__(256) void gemm_tiled_fc1(
    const float* __restrict__ X, const float* __restrict__ B,
    const float* __restrict__ bias, float* __restrict__ out)
{
    __shared__ float AsT[128*20];   // [k][t] 16 tokens + 4 pad
    const int tid  = threadIdx.x;
    const int tok0 = blockIdx.x * 16;

    #pragma unroll
    for (int i = 0; i < 8; i++){
        int idx = tid + i*256;
        int t = idx >> 7, k = idx & 127;
        AsT[k*20 + t] = X[(tok0 + t)*CDIM + k];
    }
    __syncthreads();

    float acc[16];
    #pragma unroll
    for (int t = 0; t < 16; t++) acc[t] = 0.f;
    #pragma unroll 4
    for (int k = 0; k < 128; k++){
        float w = B[k*256 + tid];
        const float4* ar = (const float4*)&AsT[k*20];
        #pragma unroll
        for (int j = 0; j < 4; j++){
            float4 a = ar[j];
            acc[4*j+0] = fmaf(a.x, w, acc[4*j+0]);
            acc[4*j+1] = fmaf(a.y, w, acc[4*j+1]);
            acc[4*j+2] = fmaf(a.z, w, acc[4*j+2]);
            acc[4*j+3] = fmaf(a.w, w, acc[4*j+3]);
        }
    }
    float bv = bias[tid];
    #pragma unroll
    for (int t = 0; t < 16; t++)
        out[(tok0+t)*256 + tid] = gelu_f(acc[t] + bv);
}

// ---------------- tensor-core flash attention, split-K partials ----------------
// Grid (NTOK/64, KSPLIT). Each CTA: 64 queries x 2048 keys -> unnormalized
// partial O (fp32) + rowwise m (log2 domain) + l.
// smem (bytes): Q/P at 0 (17408), K0 @17408, V0 @34816, K1 @52224, V1 @69632.
#define FSH_TOTAL 87040
#define KSTRB 272     // 136 bf16 per row
#define PSTRB 144     // 72  bf16 per row

__global__ __launch_bounds__(128, 2) void flash_tc(
    const bf16* __restrict__ Q, const bf16* __restrict__ K,
    const bf16* __restrict__ V,
    float* __restrict__ Opart, float* __restrict__ Mpart, float* __restrict__ Lpart)
{
    extern __shared__ char sm[];
    const uint32_t sb = (uint32_t)__cvta_generic_to_shared(sm);

    const int tid  = threadIdx.x;
    const int w    = tid >> 5;
    const int lane = tid & 31;
    const int g    = lane >> 2;      // 0..7 (row in 8)
    const int t    = lane & 3;       // 0..3 (col group)
    const int lr   = lane & 7;
    const int grp  = lane >> 3;      // 0..3 (ldmatrix group)
    const int qbase  = blockIdx.x * 64;
    const int split  = blockIdx.y;
    const int kvbase = split * KV_PER_SPLIT;

    // -- issue Q tile load --
    #pragma unroll
    for (int c = 0; c < 8; c++){
        int idx = tid + c*128;
        int row = idx >> 4, off = idx & 15;
        cpa16(sb + row*KSTRB + off*16, Q + (qbase+row)*CDIM + off*8);
    }
    cpa_commit();
    // -- issue KV tile 0 --
    #pragma unroll
    for (int c = 0; c < 8; c++){
        int idx = tid + c*128;
        int row = idx >> 4, off = idx & 15;
        cpa16(sb + 17408 + row*KSTRB + off*16, K + (kvbase+row)*CDIM + off*8);
    }
    #pragma unroll
    for (int c = 0; c < 8; c++){
        int idx = tid + c*128;
        int row = idx >> 4, off = idx & 15;
        cpa16(sb + 34816 + row*KSTRB + off*16, V + (kvbase+row)*CDIM + off*8);
    }
    cpa_commit();

    cpa_wait1();            // Q done (groups retire in order)
    __syncthreads();

    // -- Q fragments, register resident (8 k-tiles) --
    unsigned qf[8][4];
    {
        const uint32_t rb = sb + (16*w + lr + (grp&1)*8)*KSTRB;
        #pragma unroll
        for (int kt = 0; kt < 8; kt++)
            ldsm4(qf[kt], rb + (kt*16 + (grp>>1)*8)*2);
    }
    __syncthreads();        // Q region becomes P region after this

    float O[16][4];
    #pragma unroll
    for (int i = 0; i < 16; i++){ O[i][0]=0.f; O[i][1]=0.f; O[i][2]=0.f; O[i][3]=0.f; }
    float m_lo = -1e30f, m_hi = -1e30f, l_lo = 0.f, l_hi = 0.f;
    const float SC2 = 0.12751744458568204f;   // 1/(sqrt(128)*ln2)

    for (int it = 0; it < ITERS_PER_SPLIT; it++){
        if (it + 1 < ITERS_PER_SPLIT){
            const int nb = (it + 1) & 1;
            const int kb2 = kvbase + (it + 1) * 64;
            #pragma unroll
            for (int c = 0; c < 8; c++){
                int idx = tid + c*128;
                int row = idx >> 4, off = idx & 15;
                cpa16(sb + 17408 + nb*34816 + row*KSTRB + off*16, K + (kb2+row)*CDIM + off*8);
            }
            #pragma unroll
            for (int c = 0; c < 8; c++){
                int idx = tid + c*128;
                int row = idx >> 4, off = idx & 15;
                cpa16(sb + 34816 + nb*34816 + row*KSTRB + off*16, V + (kb2+row)*CDIM + off*8);
            }
            cpa_commit();
            cpa_wait1();
        } else {
            cpa_wait0();
        }
        __syncthreads();

        const uint32_t kbuf = sb + 17408 + (it & 1)*34816;
        const uint32_t vbuf = kbuf + 17408;

        // ---- S = Q K^T ----
        float s[8][4];
        #pragma unroll
        for (int i = 0; i < 8; i++){ s[i][0]=0.f; s[i][1]=0.f; s[i][2]=0.f; s[i][3]=0.f; }
        #pragma unroll
        for (int np = 0; np < 4; np++){
            const uint32_t nb_addr = kbuf + (np*16 + lr + ((grp>=2)?8:0))*KSTRB;
            #pragma unroll
            for (int kt = 0; kt < 8; kt++){
                unsigned b[4];
                ldsm4(b, nb_addr + (kt*16 + (grp&1)*8)*2);
                mma_bf16(s[2*np+0], qf[kt], b[0], b[1]);
                mma_bf16(s[2*np+1], qf[kt], b[2], b[3]);
            }
        }

        // ---- online softmax (log2 domain) ----
        #pragma unroll
        for (int i = 0; i < 8; i++){
            s[i][0] *= SC2; s[i][1] *= SC2; s[i][2] *= SC2; s[i][3] *= SC2;
        }
        float mx_lo = -1e30f, mx_hi = -1e30f;
        #pragma unroll
        for (int i = 0; i < 8; i++){
            mx_lo = fmaxf(mx_lo, fmaxf(s[i][0], s[i][1]));
            mx_hi = fmaxf(mx_hi, fmaxf(s[i][2], s[i][3]));
        }
        mx_lo = fmaxf(mx_lo, __shfl_xor_sync(0xffffffffu, mx_lo, 1));
        mx_lo = fmaxf(mx_lo, __shfl_xor_sync(0xffffffffu, mx_lo, 2));
        mx_hi = fmaxf(mx_hi, __shfl_xor_sync(0xffffffffu, mx_hi, 1));
        mx_hi = fmaxf(mx_hi, __shfl_xor_sync(0xffffffffu, mx_hi, 2));
        const float nm_lo = fmaxf(m_lo, mx_lo);
        const float nm_hi = fmaxf(m_hi, mx_hi);
        const float al_lo = ex2f(m_lo - nm_lo);
        const float al_hi = ex2f(m_hi - nm_hi);
        m_lo = nm_lo; m_hi = nm_hi;

        float sum_lo = 0.f, sum_hi = 0.f;
        #pragma unroll
        for (int i = 0; i < 8; i++){
            s[i][0] = ex2f(s[i][0] - nm_lo);
            s[i][1] = ex2f(s[i][1] - nm_lo);
            s[i][2] = ex2f(s[i][2] - nm_hi);
            s[i][3] = ex2f(s[i][3] - nm_hi);
            sum_lo += s[i][0] + s[i][1];
            sum_hi += s[i][2] + s[i][3];
        }
        sum_lo += __shfl_xor_sync(0xffffffffu, sum_lo, 1);
        sum_lo += __shfl_xor_sync(0xffffffffu, sum_lo, 2);
        sum_hi += __shfl_xor_sync(0xffffffffu, sum_hi, 1);
        sum_hi += __shfl_xor_sync(0xffffffffu, sum_hi, 2);
        l_lo = l_lo * al_lo + sum_lo;
        l_hi = l_hi * al_hi + sum_hi;

        #pragma unroll
        for (int i = 0; i < 16; i++){
            O[i][0] *= al_lo; O[i][1] *= al_lo;
            O[i][2] *= al_hi; O[i][3] *= al_hi;
        }

        // ---- write P (bf16), warp-private rows ----
        {
            unsigned* Prow  = (unsigned*)(sm + (16*w + g)*PSTRB);
            unsigned* Prow8 = (unsigned*)(sm + (16*w + g + 8)*PSTRB);
            #pragma unroll
            for (int nt = 0; nt < 8; nt++){
                Prow [nt*4 + t] = packbf(s[nt][0], s[nt][1]);
                Prow8[nt*4 + t] = packbf(s[nt][2], s[nt][3]);
            }
        }
        __syncwarp();

        // ---- O += P V ----
        unsigned pa[4][4];
        {
            const uint32_t rb = sb + (16*w + lr + (grp&1)*8)*PSTRB;
            #pragma unroll
            for (int kk = 0; kk < 4; kk++)
                ldsm4(pa[kk], rb + (kk*16 + ((grp>=2)?8:0))*2);
        }
        #pragma unroll
        for (int np = 0; np < 8; np++){
            #pragma unroll
            for (int kk = 0; kk < 4; kk++){
                unsigned b[4];
                ldsm4t(b, vbuf + (kk*16 + lr + (grp&1)*8)*KSTRB + (np*16 + ((grp>=2)?8:0))*2);
                mma_bf16(O[2*np+0], pa[kk], b[0], b[1]);
                mma_bf16(O[2*np+1], pa[kk], b[2], b[3]);
            }
        }
        __syncthreads();
    }

    // ---- epilogue: write unnormalized partials ----
    const int r_lo = qbase + 16*w + g;
    const int r_hi = r_lo + 8;
    float* Oc = Opart + (size_t)split * NTOK * CDIM;
    #pragma unroll
    for (int nt = 0; nt < 16; nt++){
        const int d0 = nt*8 + 2*t;
        Oc[r_lo*CDIM + d0]     = O[nt][0];
        Oc[r_lo*CDIM + d0 + 1] = O[nt][1];
        Oc[r_hi*CDIM + d0]     = O[nt][2];
        Oc[r_hi*CDIM + d0 + 1] = O[nt][3];
    }
    if (t == 0){
        Mpart[split*NTOK + r_lo] = m_lo;
        Lpart[split*NTOK + r_lo] = l_lo;
        Mpart[split*NTOK + r_hi] = m_hi;
        Lpart[split*NTOK + r_hi] = l_hi;
    }
}

// ---------------- split-K combine: merge partials + residual + optional GELU ----------------
__global__ __launch_bounds__(256) void combine_kernel(
    const float* __restrict__ Op, const float* __restrict__ Mp, const float* __restrict__ Lp,
    const float* __restrict__ Wres, float* __restrict__ Xout, int applyGelu)
{
    const int tok = blockIdx.x*2 + (threadIdx.x >> 7);
    const int d   = threadIdx.x & 127;

    float m0 = Mp[tok],          m1 = Mp[NTOK + tok];
    float m2 = Mp[2*NTOK + tok], m3 = Mp[3*NTOK + tok];
    float M  = fmaxf(fmaxf(m0, m1), fmaxf(m2, m3));
    float w0 = ex2f(m0 - M), w1 = ex2f(m1 - M);
    float w2 = ex2f(m2 - M), w3 = ex2f(m3 - M);
    float l  = Lp[tok]*w0 + Lp[NTOK + tok]*w1 + Lp[2*NTOK + tok]*w2 + Lp[3*NTOK + tok]*w3;

    float o = Op[(size_t)tok*CDIM + d] * w0
            + Op[(size_t)(NTOK + tok)*CDIM + d] * w1
            + Op[(size_t)(2*NTOK + tok)*CDIM + d] * w2
            + Op[(size_t)(3*NTOK + tok)*CDIM + d] * w3;

    float r = o / (l * 8192.0f) + Wres[tok*CDIM + d];
    if (applyGelu) r = gelu_f(r);
    Xout[tok*CDIM + d] = r;
}

// ---------------- local attention (bf16 inputs) ----------------
__global__ void local_attn_kernel(const bf16* __restrict__ Q, const bf16* __restrict__ K,
                                  const bf16* __restrict__ V, const float* __restrict__ Wres,
                                  const int* __restrict__ nbr, float* __restrict__ Xout)
{
    const int n    = blockIdx.x;
    const int h    = threadIdx.x >> 5;
    const int lane = threadIdx.x & 31;
    const int idx  = nbr[n*32 + lane];

    const bf16* qp = Q + n*CDIM   + h*16;
    const bf16* kp = K + idx*CDIM + h*16;
    float s = 0.f;
    #pragma unroll
    for (int d = 0; d < 16; d++)
        s = fmaf(__bfloat162float(qp[d]), __bfloat162float(kp[d]), s);
    s *= 0.25f;  // 1/sqrt(16)

    float mx = s;
    #pragma unroll
    for (int off = 16; off; off >>= 1) mx = fmaxf(mx, __shfl_xor_sync(0xffffffffu, mx, off));
    float e = __expf(s - mx);
    float tot = e;
    #pragma unroll
    for (int off = 16; off; off >>= 1) tot += __shfl_xor_sync(0xffffffffu, tot, off);
    float p = e / tot;

    const bf16* vp = V + idx*CDIM + h*16;
    float myout = 0.f;
    #pragma unroll
    for (int d = 0; d < 16; d++){
        float tsum = p * __bfloat162float(vp[d]);
        #pragma unroll
        for (int off = 16; off; off >>= 1) tsum += __shfl_xor_sync(0xffffffffu, tsum, off);
        if (lane == d) myout = tsum;
    }
    if (lane < 16){
        int o = n*CDIM + h*16 + lane;
        Xout[o] = gelu_f(myout + Wres[o]);
    }
}

// ---------------- fc2 ----------------
__global__ void fc2_kernel(const float* __restrict__ Y, const float* __restrict__ w,
                           const float* __restrict__ b, float* __restrict__ out)
{
    const int gw   = (blockIdx.x * blockDim.x + threadIdx.x) >> 5;
    const int lane = threadIdx.x & 31;
    if (gw >= NTOK) return;
    const float* yr = Y + gw*256;
    float acc = 0.f;
    #pragma unroll
    for (int c = 0; c < 8; c++) acc = fmaf(yr[lane + 32*c], w[lane + 32*c], acc);
    #pragma unroll
    for (int off = 16; off; off >>= 1) acc += __shfl_xor_sync(0xffffffffu, acc, off);
    if (lane == 0) out[gw] = acc + b[0];
}

extern "C" void kernel_launch(void* const* d_in, const int* in_sizes, int n_in,
                              void* d_out, int out_size)
{
    const float* x    = (const float*)d_in[0];
    const float* fc0w = (const float*)d_in[1];
    const float* fc0b = (const float*)d_in[2];
    const float* fc1w = (const float*)d_in[27];
    const float* fc1b = (const float*)d_in[28];
    const float* fc2w = (const float*)d_in[29];
    const float* fc2b = (const float*)d_in[30];
    const int*   nbr  = (const int*)d_in[31];
    float* out = (float*)d_out;

    float *X, *Wp, *Y1, *Op, *Mp, *Lp;
    bf16 *Qh, *Kh, *Vh;
    cudaGetSymbolAddress((void**)&X,  g_X);
    cudaGetSymbolAddress((void**)&Qh, g_Qh);
    cudaGetSymbolAddress((void**)&Kh, g_Kh);
    cudaGetSymbolAddress((void**)&Vh, g_Vh);
    cudaGetSymbolAddress((void**)&Wp, g_W);
    cudaGetSymbolAddress((void**)&Y1, g_Y1);
    cudaGetSymbolAddress((void**)&Op, g_Op);
    cudaGetSymbolAddress((void**)&Mp, g_Mp);
    cudaGetSymbolAddress((void**)&Lp, g_Lp);

    cudaFuncSetAttribute(flash_tc, cudaFuncAttributeMaxDynamicSharedMemorySize, FSH_TOTAL);

    // fc0: [8192,3] @ [3,128] + b
    gemm_row<<<NTOK, 128>>>(x, fc0w, fc0b, X, 3, CDIM);

    for (int layer = 0; layer < 3; layer++){
        const int base = 3 + layer*8;
        qkvw_tiled<<<dim3(NTOK/32, 4), 128>>>(X,
            (const float*)d_in[base+0], (const float*)d_in[base+1],
            (const float*)d_in[base+2], (const float*)d_in[base+3],
            (const float*)d_in[base+4], (const float*)d_in[base+5],
            (const float*)d_in[base+6], (const float*)d_in[base+7],
            Qh, Kh, Vh, Wp);

        if (layer == 1){
            local_attn_kernel<<<NTOK, 256>>>(Qh, Kh, Vh, Wp, nbr, X);
        } else {
            flash_tc<<<dim3(NTOK/64, KSPLIT), 128, FSH_TOTAL>>>(Qh, Kh, Vh, Op, Mp, Lp);
            combine_kernel<<<NTOK/2, 256>>>(Op, Mp, Lp, Wp, X, (layer == 0) ? 1 : 0);
        }
    }

    gemm_tiled_fc1<<<NTOK/16, 256>>>(X, fc1w, fc1b, Y1);
    fc2_kernel<<<NTOK*32/256, 256>>>(Y1, fc2w, fc2b, out);
}